// round 2
// baseline (speedup 1.0000x reference)
#include <cuda_runtime.h>
#include <cuda_bf16.h>

// Contamination: out = 0.8*x + 0.2 * avg(valid neighbors at offsets {±8,0}x{±8,0}\{0,0})
// x: [B=8, C=32, H=512, W=512] fp32, k=8.
//
// R2: rolling-register row reuse. Each thread's 4 output rows step by exactly
// 8 = the neighbor offset, so the per-row 3-column horizontal sum is computed
// ONCE per row and rolled (prev/cur/next). 6 row-loads x 3 cols = 18 LDG.128
// per thread vs 36 in R1 -> halves L1tex/LSU work, same compulsory DRAM
// traffic, more exposed MLP.

namespace {

constexpr int H  = 512;
constexpr int W  = 512;
constexpr int K  = 8;
constexpr int W4 = W / 4;       // 128 float4 per row

struct RowRS {
    float4 sum;   // horizontal 3-column sum (center + left8 + right8), zeros if row invalid
    float4 ctr;   // center column value
};

__device__ __forceinline__ float4 f4add(float4 a, float4 b) {
    return make_float4(a.x + b.x, a.y + b.y, a.z + b.z, a.w + b.w);
}

__device__ __forceinline__ RowRS load_row(const float4* __restrict__ pin,
                                          int r, int c4, bool hasL, bool hasR) {
    RowRS o;
    o.sum = make_float4(0.f, 0.f, 0.f, 0.f);
    o.ctr = o.sum;
    if (r >= 0 && r < H) {
        const float4* __restrict__ row = pin + (long)r * W4;
        float4 c = row[c4];
        float4 s = c;
        if (hasL) s = f4add(s, row[c4 - 2]);
        if (hasR) s = f4add(s, row[c4 + 2]);
        o.ctr = c;
        o.sum = s;
    }
    return o;
}

__global__ __launch_bounds__(256, 6)
void contam_kernel(const float4* __restrict__ in, float4* __restrict__ out) {
    const int c4   = blockIdx.x * 32 + threadIdx.x;   // float4 column, 0..127
    const int row0 = blockIdx.y * 32 + threadIdx.y;   // first output row of this thread
    const long plane = blockIdx.z;

    const float4* __restrict__ pin  = in  + plane * (long)(H * W4);
    float4* __restrict__       pout = out + plane * (long)(H * W4);

    const bool hasL = (c4 >= 2);
    const bool hasR = (c4 <= W4 - 3);
    const int  nc   = 1 + (int)hasL + (int)hasR;

    // rolling state: rows h-8 (prev), h (cur), h+8 (next)
    RowRS prev = load_row(pin, row0 - K, c4, hasL, hasR);
    RowRS cur  = load_row(pin, row0,     c4, hasL, hasR);

    #pragma unroll
    for (int ry = 0; ry < 4; ry++) {
        const int h = row0 + ry * K;

        // issue next-row loads early so they overlap the arithmetic below
        RowRS next = load_row(pin, h + K, c4, hasL, hasR);

        const int nr = 1 + (int)(h >= K) + (int)(h < H - K);
        const float inv_cnt = 1.0f / (float)(nr * nc - 1);

        float4 acc = f4add(f4add(prev.sum, cur.sum), next.sum);
        float4 ctr = cur.ctr;

        float4 o;
        o.x = 0.8f * ctr.x + 0.2f * (acc.x - ctr.x) * inv_cnt;
        o.y = 0.8f * ctr.y + 0.2f * (acc.y - ctr.y) * inv_cnt;
        o.z = 0.8f * ctr.z + 0.2f * (acc.z - ctr.z) * inv_cnt;
        o.w = 0.8f * ctr.w + 0.2f * (acc.w - ctr.w) * inv_cnt;

        pout[(long)h * W4 + c4] = o;

        prev = cur;
        cur  = next;
    }
}

} // namespace

extern "C" void kernel_launch(void* const* d_in, const int* in_sizes, int n_in,
                              void* d_out, int out_size) {
    const float4* x = (const float4*)d_in[0];
    float4* out = (float4*)d_out;

    const int planes = in_sizes[0] / (H * W);   // 256

    dim3 block(32, 8, 1);
    dim3 grid(W4 / 32, H / 32, planes);         // (4, 16, 256)
    contam_kernel<<<grid, block>>>(x, out);
}

// round 3
// speedup vs baseline: 1.2608x; 1.2608x over previous
#include <cuda_runtime.h>
#include <cuda_bf16.h>

// Contamination: out = 0.8*x + 0.2 * avg(valid neighbors at offsets {-8,0,8}^2 \ {0,0})
// x: [B=8, C=32, H=512, W=512] fp32, k=8.
//
// R3: rolling horizontal-sum reuse (4 L1 ops/output vs R1's 9), but:
//  - roll carries ONLY the 3-col sums (12 regs), ctr is re-loaded (L1 hit)
//  - launch_bounds(256,7) -> <=36 regs -> 56 warps/SM
//  - all 4 loads of an iteration issued together (batched, independent)
//  - streaming stores (__stcs) keep never-re-read output out of L2

namespace {

constexpr int H  = 512;
constexpr int W  = 512;
constexpr int K  = 8;
constexpr int W4 = W / 4;       // 128 float4 per row

__device__ __forceinline__ float4 f4add(float4 a, float4 b) {
    return make_float4(a.x + b.x, a.y + b.y, a.z + b.z, a.w + b.w);
}

// horizontal 3-column sum for row r (zeros if r out of range)
__device__ __forceinline__ float4 hsum_row(const float4* __restrict__ pin,
                                           int r, int c4, bool hasL, bool hasR) {
    float4 s = make_float4(0.f, 0.f, 0.f, 0.f);
    if (r >= 0 && r < H) {
        const float4* __restrict__ row = pin + (long)r * W4;
        s = row[c4];
        if (hasL) s = f4add(s, row[c4 - 2]);
        if (hasR) s = f4add(s, row[c4 + 2]);
    }
    return s;
}

__global__ __launch_bounds__(256, 7)
void contam_kernel(const float4* __restrict__ in, float4* __restrict__ out) {
    const int c4   = blockIdx.x * 32 + threadIdx.x;   // float4 column, 0..127
    const int row0 = blockIdx.y * 32 + threadIdx.y;   // first output row
    const long plane = blockIdx.z;

    const float4* __restrict__ pin  = in  + plane * (long)(H * W4);
    float4* __restrict__       pout = out + plane * (long)(H * W4);

    const bool hasL = (c4 >= 2);
    const bool hasR = (c4 <= W4 - 3);
    const int  nc   = 1 + (int)hasL + (int)hasR;

    float4 Sprev = hsum_row(pin, row0 - K, c4, hasL, hasR);
    float4 Scur  = hsum_row(pin, row0,     c4, hasL, hasR);

    #pragma unroll
    for (int ry = 0; ry < 4; ry++) {
        const int h  = row0 + ry * K;
        const int rn = h + K;
        const bool vn = (rn < H);

        // ---- batched loads: 3 next-row cols + ctr, all independent ----
        const float4* __restrict__ rowN = pin + (long)(vn ? rn : h) * W4;
        float4 n1 = rowN[c4];                                     // next center col
        float4 n0 = hasL ? rowN[c4 - 2] : make_float4(0,0,0,0);   // next left
        float4 n2 = hasR ? rowN[c4 + 2] : make_float4(0,0,0,0);   // next right
        float4 ctr = pin[(long)h * W4 + c4];                      // L1 hit (reload)

        float4 Snext = vn ? f4add(f4add(n1, n0), n2)
                          : make_float4(0.f, 0.f, 0.f, 0.f);

        const int nr = 1 + (int)(h >= K) + (int)vn;
        const float inv_cnt = 1.0f / (float)(nr * nc - 1);

        float4 acc = f4add(f4add(Sprev, Scur), Snext);

        float4 o;
        o.x = 0.8f * ctr.x + 0.2f * (acc.x - ctr.x) * inv_cnt;
        o.y = 0.8f * ctr.y + 0.2f * (acc.y - ctr.y) * inv_cnt;
        o.z = 0.8f * ctr.z + 0.2f * (acc.z - ctr.z) * inv_cnt;
        o.w = 0.8f * ctr.w + 0.2f * (acc.w - ctr.w) * inv_cnt;

        __stcs(&pout[(long)h * W4 + c4], o);

        Sprev = Scur;
        Scur  = Snext;
    }
}

} // namespace

extern "C" void kernel_launch(void* const* d_in, const int* in_sizes, int n_in,
                              void* d_out, int out_size) {
    const float4* x = (const float4*)d_in[0];
    float4* out = (float4*)d_out;

    const int planes = in_sizes[0] / (H * W);   // 256

    dim3 block(32, 8, 1);
    dim3 grid(W4 / 32, H / 32, planes);         // (4, 16, 256)
    contam_kernel<<<grid, block>>>(x, out);
}